// round 1
// baseline (speedup 1.0000x reference)
#include <cuda_runtime.h>
#include <math.h>

#define MAX_ROWS 65536
#define QI 512
#define QF 512.0f

// Scratch (no cudaMalloc allowed): per-row lambda and mu0 = -log(S0)
__device__ float g_lam[MAX_ROWS];
__device__ float g_mu0[MAX_ROWS];

// c(x) = coth(x) - 1/x, cox = c(x)/x.  Stable for all x (odd, smooth at 0).
__device__ __forceinline__ void cfun(float x, float& c, float& cox) {
    float ax = fabsf(x);
    if (ax < 0.5f) {
        // c(x)/x = 1/3 - x^2/45 + 2x^4/945 - x^6/4725  (trunc err < 1e-7 at |x|=0.5)
        float x2 = x * x;
        cox = 0.33333334f + x2 * (-0.022222223f + x2 * (0.0021164021f + x2 * (-2.1164021e-4f)));
        c = x * cox;
    } else {
        float e = __expf(2.0f * x);           // x in [-~16, ~16] after clamp; guard inf anyway
        float coth = isinf(e) ? 1.0f : __fdividef(e + 1.0f, e - 1.0f);
        float ix = __fdividef(1.0f, x);
        c = coth - ix;
        cox = c * ix;
    }
}

// mean index and variance index of the discrete exp-tilted distribution on {0..Q-1}
__device__ __forceinline__ void moments(float t, float& mu, float& var) {
    float c1, c1x, cQ, cQx;
    cfun(0.5f * t, c1, c1x);          // c(t/2)
    cfun(256.0f * t, cQ, cQx);        // c(Q*t/2), Q=512
    mu = 255.5f + 0.5f * (QF * cQ - c1);
    float cp1 = 1.0f - 2.0f * c1x - c1 * c1;   // c'(t/2)
    float cpQ = 1.0f - 2.0f * cQx - cQ * cQ;   // c'(Qt/2)
    var = 0.25f * (262144.0f * cpQ - cp1);     // Q^2 = 262144
}

__global__ void solve_kernel(const float* __restrict__ vel,
                             const float* __restrict__ xi, int n) {
    int i = blockIdx.x * blockDim.x + threadIdx.x;
    if (i >= n) return;
    float h = xi[1] - xi[0];                 // 70/511
    float target = __fdividef(vel[i], h);    // target mean index in [~36.5, ~474.5]
    float t = 0.0f;                          // t = lambda * h
    #pragma unroll 1
    for (int it = 0; it < 12; ++it) {        // converges in <=10; extra iters are no-ops
        float mu, var;
        moments(t, mu, var);
        t -= __fdividef(mu - target, var);
        t = fminf(0.06f, fmaxf(-0.06f, t));  // true root |t| <= ~0.028 for v in [5,65]
    }
    // log S0 = log( (e^{Qt}-1)/(e^t-1) ), stable via expm1 (accurate path for output)
    float logS0;
    if (fabsf(t) < 1e-12f) {
        logS0 = logf(QF) + 255.5f * t;
    } else {
        logS0 = logf(expm1f(QF * t) / expm1f(t));
    }
    g_lam[i] = t / h;
    g_mu0[i] = -logS0;
}

// One warp per row. Lane l owns elements j = 4l + 128k, k=0..3 (coalesced float4 stores).
// One accurate expf anchor per lane; geometric ladder via r, r^2, r^3 and R = r^128 jumps.
__global__ void write_kernel(const float* __restrict__ xi,
                             float* __restrict__ out, int n) {
    int gid = blockIdx.x * blockDim.x + threadIdx.x;
    int row = gid >> 5;
    int lane = gid & 31;
    if (row >= n) return;
    float lam = g_lam[row];
    float mu0 = g_mu0[row];
    float h = xi[1] - xi[0];
    float r = 0.0f, R = 0.0f;
    if (lane == 0) {                          // 2 exps per row, broadcast
        float lh = lam * h;
        r = expf(lh);
        R = expf(lh * 128.0f);
    }
    r = __shfl_sync(0xffffffffu, r, 0);
    R = __shfl_sync(0xffffffffu, R, 0);
    float r2 = r * r;
    float r3 = r2 * r;
    int j0 = lane << 2;
    float v = expf(fmaf(lam, __ldg(&xi[j0]), mu0));   // anchor at true xi value
    float4* o = reinterpret_cast<float4*>(out) + (size_t)row * 128;
    #pragma unroll
    for (int k = 0; k < 4; ++k) {
        float4 val = make_float4(v, v * r, v * r2, v * r3);
        o[lane + (k << 5)] = val;             // lanes consecutive -> 512B/instr coalesced
        v *= R;
    }
}

extern "C" void kernel_launch(void* const* d_in, const int* in_sizes, int n_in,
                              void* d_out, int out_size) {
    const float* vel = (const float*)d_in[0];
    const float* xi  = (const float*)d_in[1];
    int n = in_sizes[0];
    if (n_in >= 2 && in_sizes[0] < in_sizes[1]) {   // defensive: xi is the small (Q=512) buffer
        vel = (const float*)d_in[1];
        xi  = (const float*)d_in[0];
        n = in_sizes[1];
    }
    if (n > MAX_ROWS) n = MAX_ROWS;
    float* out = (float*)d_out;

    solve_kernel<<<(n + 255) / 256, 256>>>(vel, xi, n);

    // one warp per row, 8 warps (rows) per 256-thread block
    int blocks = (n + 7) / 8;
    write_kernel<<<blocks, 256>>>(xi, out, n);
}